// round 4
// baseline (speedup 1.0000x reference)
#include <cuda_runtime.h>

#define T_STEPS 512
#define HID 64

typedef unsigned long long ull;

// packed fp32x2 FMA: d.lo += a.lo*b.lo ; d.hi += a.hi*b.hi  (Blackwell FFMA2, PTX-only)
__device__ __forceinline__ void fma2(ull &d, ull a, ull b) {
    asm("fma.rn.f32x2 %0, %1, %2, %0;" : "+l"(d) : "l"(a), "l"(b));
}
__device__ __forceinline__ ull add2(ull a, ull b) {
    ull r;
    asm("add.rn.f32x2 %0, %1, %2;" : "=l"(r) : "l"(a), "l"(b));
    return r;
}
__device__ __forceinline__ float hsum2(ull v) {
    float lo, hi;
    asm("mov.b64 {%0,%1}, %2;" : "=f"(lo), "=f"(hi) : "l"(v));
    return lo + hi;
}

// tanh(x) = 1 - 2/(e^{2x}+1): MUFU.EX2 + MUFU.RCP path, abs err ~1e-7.
__device__ __forceinline__ float tanh_fast(float x) {
    float xc = fminf(fmaxf(x, -10.0f), 10.0f);
    float e  = __expf(xc + xc);
    return 1.0f - __fdividef(2.0f, e + 1.0f);
}

// K-split decomposition: CTA = 2 warps = 2 batches (A, B).
//   warp w owns K-columns [32w, 32w+32) of W_hh rows (lane, lane+32): 64 W regs/thread.
//   Each step: both warps compute half-K partial dots for BOTH batches,
//   exchange partials via shared, warp0 finalizes batch A, warp1 batch B.
// 2048 warps total -> 13.8 warps/SM (3.46/SMSP), single wave, ~105 regs (no spill).
__global__ void rnn_ksplit_kernel(const float* __restrict__ x,
                                  const float* __restrict__ W_ih,
                                  const float* __restrict__ W_hh,
                                  const float* __restrict__ b_ih,
                                  const float* __restrict__ b_hh,
                                  const float* __restrict__ fc_w,
                                  const float* __restrict__ fc_b,
                                  float* __restrict__ out)
{
    __shared__ __align__(16) float sx[2][T_STEPS];     // x for batches A, B
    __shared__ __align__(16) float hsh[2][HID];        // h for batches A, B (single buffer; bar-protected)
    __shared__ __align__(16) float pbuf[2][HID];       // partial exchange: [batch][row]

    const int lane = threadIdx.x & 31;
    const int w    = threadIdx.x >> 5;                 // warp 0 or 1
    const int b0   = 2 * blockIdx.x;

    // W_hh rows (lane, lane+32), cols [32w, 32w+32), as f32x2 pairs: 32 ull = 64 regs.
    ull w0[16], w1[16];
    {
        const ull* wr0 = reinterpret_cast<const ull*>(W_hh + lane * HID + 32 * w);
        const ull* wr1 = reinterpret_cast<const ull*>(W_hh + (lane + 32) * HID + 32 * w);
#pragma unroll
        for (int p = 0; p < 16; ++p) { w0[p] = wr0[p]; w1[p] = wr1[p]; }
    }

    const float wih0  = W_ih[lane];
    const float wih1  = W_ih[lane + 32];
    const float bias0 = b_ih[lane]      + b_hh[lane];
    const float bias1 = b_ih[lane + 32] + b_hh[lane + 32];

    // Stage both x sequences (I=1 => contiguous 512 floats each). 64 threads, 256 float4.
    {
        const float4* xg = reinterpret_cast<const float4*>(x + (size_t)b0 * T_STEPS);
        float4* s = reinterpret_cast<float4*>(&sx[0][0]);
#pragma unroll
        for (int i = 0; i < 4; ++i) s[threadIdx.x + 64 * i] = xg[threadIdx.x + 64 * i];
    }

    // h = 0
    hsh[0][threadIdx.x] = 0.0f;
    hsh[1][threadIdx.x] = 0.0f;
    __syncthreads();

    // Per-warp finalization targets (uniform within warp -> no divergence cost).
    float* hw_mine  = hsh[w];         // warp w finalizes batch w
    float* pb_read  = pbuf[w];        // partner's partials for my batch
    float* pb_write = pbuf[1 - w];    // my partials for partner's batch
    const float* x_mine = sx[w];
    const ulonglong2* hpA = reinterpret_cast<const ulonglong2*>(&hsh[0][32 * w]);
    const ulonglong2* hpB = reinterpret_cast<const ulonglong2*>(&hsh[1][32 * w]);

#pragma unroll 1
    for (int t = 0; t < T_STEPS; ++t) {
        // Half-K partial dots for both batches; 8 independent FFMA2 chains (depth 8).
        ull A0a = 0, A0b = 0, A1a = 0, A1b = 0;
        ull B0a = 0, B0b = 0, B1a = 0, B1b = 0;
#pragma unroll
        for (int k = 0; k < 8; ++k) {
            ulonglong2 ha = hpA[k];                 // LDS.128 broadcast
            ulonglong2 hb = hpB[k];
            fma2(A0a, ha.x, w0[2 * k]);  fma2(A0b, ha.y, w0[2 * k + 1]);
            fma2(A1a, ha.x, w1[2 * k]);  fma2(A1b, ha.y, w1[2 * k + 1]);
            fma2(B0a, hb.x, w0[2 * k]);  fma2(B0b, hb.y, w0[2 * k + 1]);
            fma2(B1a, hb.x, w1[2 * k]);  fma2(B1b, hb.y, w1[2 * k + 1]);
        }
        float pA0 = hsum2(add2(A0a, A0b));          // rows lane, lane+32, batch A
        float pA1 = hsum2(add2(A1a, A1b));
        float pB0 = hsum2(add2(B0a, B0b));          // batch B
        float pB1 = hsum2(add2(B1a, B1b));

        // Write my partials for the batch my partner finalizes.
        float po0 = w ? pA0 : pB0;                  // warp0 exports B, warp1 exports A
        float po1 = w ? pA1 : pB1;
        pb_write[lane]      = po0;
        pb_write[lane + 32] = po1;
        __syncthreads();                            // BAR1: h-reads done, partials visible

        // Finalize my batch: own partial + partner partial + x*W_ih + biases -> tanh -> h.
        float own0 = w ? pB0 : pA0;
        float own1 = w ? pB1 : pA1;
        float xt = x_mine[t];
        float s0 = own0 + pb_read[lane]      + fmaf(xt, wih0, bias0);
        float s1 = own1 + pb_read[lane + 32] + fmaf(xt, wih1, bias1);
        hw_mine[lane]      = tanh_fast(s0);
        hw_mine[lane + 32] = tanh_fast(s1);
        __syncthreads();                            // BAR2: new h visible for next step
    }

    // Final FC for both batches (warp 0 only): out[b] = sum_h hT[h]*fc_w[h] + fc_b
    if (w == 0) {
        const float fw0 = fc_w[lane], fw1 = fc_w[lane + 32];
        float vA = fmaf(hsh[0][lane], fw0, hsh[0][lane + 32] * fw1);
        float vB = fmaf(hsh[1][lane], fw0, hsh[1][lane + 32] * fw1);
#pragma unroll
        for (int o = 16; o; o >>= 1) {
            vA += __shfl_xor_sync(0xffffffffu, vA, o);
            vB += __shfl_xor_sync(0xffffffffu, vB, o);
        }
        if (lane == 0) {
            float fb = fc_b[0];
            out[b0]     = vA + fb;
            out[b0 + 1] = vB + fb;
        }
    }
}

extern "C" void kernel_launch(void* const* d_in, const int* in_sizes, int n_in,
                              void* d_out, int out_size)
{
    const float* x    = (const float*)d_in[0];  // [B, T, 1]
    const float* W_ih = (const float*)d_in[1];  // [64, 1]
    const float* W_hh = (const float*)d_in[2];  // [64, 64]
    const float* b_ih = (const float*)d_in[3];  // [64]
    const float* b_hh = (const float*)d_in[4];  // [64]
    const float* fc_w = (const float*)d_in[5];  // [1, 64]
    const float* fc_b = (const float*)d_in[6];  // [1]
    float* out = (float*)d_out;                 // [B, 1]

    int B = in_sizes[0] / T_STEPS;              // I == 1
    rnn_ksplit_kernel<<<B / 2, 64>>>(x, W_ih, W_hh, b_ih, b_hh, fc_w, fc_b, out);
}

// round 5
// speedup vs baseline: 1.1327x; 1.1327x over previous
#include <cuda_runtime.h>

#define T_STEPS 512
#define HID 64

typedef unsigned long long ull;

// packed fp32x2 FMA: d.lo += a.lo*b.lo ; d.hi += a.hi*b.hi  (Blackwell FFMA2, PTX-only)
__device__ __forceinline__ void fma2(ull &d, ull a, ull b) {
    asm("fma.rn.f32x2 %0, %1, %2, %0;" : "+l"(d) : "l"(a), "l"(b));
}
__device__ __forceinline__ ull add2(ull a, ull b) {
    ull r;
    asm("add.rn.f32x2 %0, %1, %2;" : "=l"(r) : "l"(a), "l"(b));
    return r;
}
__device__ __forceinline__ float hsum2(ull v) {
    float lo, hi;
    asm("mov.b64 {%0,%1}, %2;" : "=f"(lo), "=f"(hi) : "l"(v));
    return lo + hi;
}

// tanh(x) = 1 - 2/(e^{2x}+1): MUFU.EX2 + MUFU.RCP path, abs err ~1e-7.
__device__ __forceinline__ float tanh_fast(float x) {
    float xc = fminf(fmaxf(x, -10.0f), 10.0f);
    float e  = __expf(xc + xc);
    return 1.0f - __fdividef(2.0f, e + 1.0f);
}

// One warp, two batches (A, B), software-pipelined one step apart:
//   region1: FFMA(A,t)   overlapped with tail finalizing h_B(t-1)
//   region2: FFMA(B,t-1) overlapped with tail finalizing h_A(t)
// The tanh/hsum/STS tail of one batch hides under the 64-FFMA2 issue stream of
// the other, removing the exposed serial tail that held R2/R3 at 2x the FFMA floor.
// W_hh rows (lane, lane+32) register-resident (128 regs), grid=1024, single wave.
__global__ void rnn_pipe_kernel(const float* __restrict__ x,
                                const float* __restrict__ W_ih,
                                const float* __restrict__ W_hh,
                                const float* __restrict__ b_ih,
                                const float* __restrict__ b_hh,
                                const float* __restrict__ fc_w,
                                const float* __restrict__ fc_b,
                                float* __restrict__ out)
{
    __shared__ __align__(16) float sxA[T_STEPS];
    __shared__ __align__(16) float sxB[T_STEPS];
    __shared__ __align__(16) float hA[HID];
    __shared__ __align__(16) float hB[HID];

    const int lane = threadIdx.x;        // lane owns output rows (lane, lane+32)
    const int b0   = 2 * blockIdx.x;     // batches A=b0, B=b0+1

    // W_hh rows `lane` and `lane+32` as f32x2 j-pairs (128 regs).
    ull w0[32], w1[32];
    {
        const ull* wr0 = reinterpret_cast<const ull*>(W_hh + lane * HID);
        const ull* wr1 = reinterpret_cast<const ull*>(W_hh + (lane + 32) * HID);
#pragma unroll
        for (int p = 0; p < 32; ++p) { w0[p] = wr0[p]; w1[p] = wr1[p]; }
    }

    const float wih0  = W_ih[lane];
    const float wih1  = W_ih[lane + 32];
    const float bias0 = b_ih[lane]      + b_hh[lane];
    const float bias1 = b_ih[lane + 32] + b_hh[lane + 32];

    // Stage both x sequences (I=1 => contiguous 512 floats each).
    {
        const float4* xg  = reinterpret_cast<const float4*>(x + (size_t)b0 * T_STEPS);
        float4* sA = reinterpret_cast<float4*>(sxA);
        float4* sB = reinterpret_cast<float4*>(sxB);
#pragma unroll
        for (int i = 0; i < 4; ++i) {
            sA[lane + 32 * i] = xg[lane + 32 * i];
            sB[lane + 32 * i] = xg[128 + lane + 32 * i];
        }
        __syncwarp();  // sx visible before reading x values below
    }

    // h_A(0) = tanh(xp_A(0)) since h(-1)=0; B's pipeline starts with zero partials.
    hA[lane]      = tanh_fast(fmaf(sxA[0], wih0, bias0));
    hA[lane + 32] = tanh_fast(fmaf(sxA[0], wih1, bias1));
    // accB = W.h_B(-1) = 0 partials; region1 of t=1 finalizes h_B(0)=tanh(xp_B(0)).
    ull B0a = 0, B0b = 0, B1a = 0, B1b = 0;
    __syncwarp();

    const ulonglong2* hpA = reinterpret_cast<const ulonglong2*>(hA);
    const ulonglong2* hpB = reinterpret_cast<const ulonglong2*>(hB);

#pragma unroll 1
    for (int t = 1; t < T_STEPS; ++t) {
        // ── region 1: FFMA(A,t) over h_A(t-1)  ∥  tail h_B(t-1) from carried accB ──
        ull A0a = 0, A0b = 0, A1a = 0, A1b = 0;
#pragma unroll
        for (int k = 0; k < 16; ++k) {
            ulonglong2 h2 = hpA[k];                 // LDS.128 broadcast
            fma2(A0a, h2.x, w0[2 * k]);  fma2(A0b, h2.y, w0[2 * k + 1]);
            fma2(A1a, h2.x, w1[2 * k]);  fma2(A1b, h2.y, w1[2 * k + 1]);
        }
        {
            float xb = sxB[t - 1];
            float s0 = hsum2(add2(B0a, B0b)) + fmaf(xb, wih0, bias0);
            float s1 = hsum2(add2(B1a, B1b)) + fmaf(xb, wih1, bias1);
            hB[lane]      = tanh_fast(s0);
            hB[lane + 32] = tanh_fast(s1);
        }
        __syncwarp();   // hB(t-1) visible; hA reads done before region2 overwrites hA

        // ── region 2: FFMA(B,t-1) over h_B(t-1)  ∥  tail h_A(t) from accA ──
        B0a = 0; B0b = 0; B1a = 0; B1b = 0;
#pragma unroll
        for (int k = 0; k < 16; ++k) {
            ulonglong2 h2 = hpB[k];
            fma2(B0a, h2.x, w0[2 * k]);  fma2(B0b, h2.y, w0[2 * k + 1]);
            fma2(B1a, h2.x, w1[2 * k]);  fma2(B1b, h2.y, w1[2 * k + 1]);
        }
        {
            float xa = sxA[t];
            float s0 = hsum2(add2(A0a, A0b)) + fmaf(xa, wih0, bias0);
            float s1 = hsum2(add2(A1a, A1b)) + fmaf(xa, wih1, bias1);
            hA[lane]      = tanh_fast(s0);
            hA[lane + 32] = tanh_fast(s1);
        }
        __syncwarp();   // hA(t) + hB reads ordered before next iteration
    }

    // Epilogue: finalize h_B(T-1) from the carried accB (stays in registers).
    float xb = sxB[T_STEPS - 1];
    float hBf0 = tanh_fast(hsum2(add2(B0a, B0b)) + fmaf(xb, wih0, bias0));
    float hBf1 = tanh_fast(hsum2(add2(B1a, B1b)) + fmaf(xb, wih1, bias1));

    // Final FC: out[b] = sum_h hT[h]*fc_w[h] + fc_b
    const float fw0 = fc_w[lane], fw1 = fc_w[lane + 32];
    float vA = fmaf(hA[lane], fw0, hA[lane + 32] * fw1);
    float vB = fmaf(hBf0,     fw0, hBf1          * fw1);
#pragma unroll
    for (int o = 16; o; o >>= 1) {
        vA += __shfl_xor_sync(0xffffffffu, vA, o);
        vB += __shfl_xor_sync(0xffffffffu, vB, o);
    }
    if (lane == 0) {
        float fb = fc_b[0];
        out[b0]     = vA + fb;
        out[b0 + 1] = vB + fb;
    }
}

extern "C" void kernel_launch(void* const* d_in, const int* in_sizes, int n_in,
                              void* d_out, int out_size)
{
    const float* x    = (const float*)d_in[0];  // [B, T, 1]
    const float* W_ih = (const float*)d_in[1];  // [64, 1]
    const float* W_hh = (const float*)d_in[2];  // [64, 64]
    const float* b_ih = (const float*)d_in[3];  // [64]
    const float* b_hh = (const float*)d_in[4];  // [64]
    const float* fc_w = (const float*)d_in[5];  // [1, 64]
    const float* fc_b = (const float*)d_in[6];  // [1]
    float* out = (float*)d_out;                 // [B, 1]

    int B = in_sizes[0] / T_STEPS;              // I == 1
    rnn_pipe_kernel<<<B / 2, 32>>>(x, W_ih, W_hh, b_ih, b_hh, fc_w, fc_b, out);
}